// round 8
// baseline (speedup 1.0000x reference)
#include <cuda_runtime.h>
#include <cuda_fp16.h>
#include <cstdint>

#define BN_EPS 1e-5f

constexpr int N_    = 32;   // points per polyline
constexpr int C_    = 9;    // input channels
constexpr int H_    = 64;   // hidden
constexpr int OUT_  = 128;
constexpr int SAWH  = 36;   // X tile row stride in half2-words -> conflict-free frags
constexpr int SPWH  = 12;   // P tile row stride in half2-words -> conflict-free
constexpr int SVH   = 36;   // row stride (half2 words) for [4][32] pooled / H4 mats
constexpr int SVW   = 68;   // row stride (f32) for sT

// -------- device scratch (no allocations allowed) --------
__device__ float    g_b0v[H_], g_b1v[H_], g_b2v[H_];
__device__ uint32_t g_W0h[512];         // folded Wpre (k padded to 16), fp16 B-frag
__device__ uint32_t g_W1h[2048];        // folded W1 low half  (k 0..63), fp16 B-frag
__device__ uint32_t g_W1hh[2048];       // folded W1 high half (k 64..127), fp16 B-frag
__device__ uint32_t g_W2h[2048];        // folded W2, fp16 B-frag
__device__ uint32_t g_W3h[2048];        // raw W3, fp16 B-frag
__device__ uint32_t g_W4h[4096];        // raw W4 [64][128], fp16 B-frag
__device__ int      g_mask4;            // 1 if mask elements are 4 bytes wide

__device__ __forceinline__ uint32_t packh2(float a, float b) {
    __half2 h = __floats2half2_rn(a, b);
    return *(uint32_t*)&h;
}
__device__ __forceinline__ uint32_t h2bits(__half2 v) { return *(uint32_t*)&v; }
__device__ __forceinline__ __half2  bits2h(uint32_t u) { return *(__half2*)&u; }

__device__ __forceinline__ void mma_f16(float& c0, float& c1, float& c2, float& c3,
                                        uint32_t a0, uint32_t a1, uint32_t a2, uint32_t a3,
                                        uint32_t b0, uint32_t b1) {
    asm volatile(
        "mma.sync.aligned.m16n8k16.row.col.f32.f16.f16.f32 "
        "{%0,%1,%2,%3},{%4,%5,%6,%7},{%8,%9},{%0,%1,%2,%3};\n"
        : "+f"(c0), "+f"(c1), "+f"(c2), "+f"(c3)
        : "r"(a0), "r"(a1), "r"(a2), "r"(a3), "r"(b0), "r"(b1));
}

// ldmatrix x4: loads the full m16xk16 fp16 A fragment in one instruction.
__device__ __forceinline__ void ldsm4(uint32_t& r0, uint32_t& r1, uint32_t& r2, uint32_t& r3,
                                      uint32_t saddr) {
    asm volatile("ldmatrix.sync.aligned.m8n8.x4.shared.b16 {%0,%1,%2,%3}, [%4];"
                 : "=r"(r0), "=r"(r1), "=r"(r2), "=r"(r3) : "r"(saddr));
}

#define BARP(id) asm volatile("bar.sync %0, %1;" :: "r"(id), "r"(64) : "memory")

// ============================================================
// Fold BN into weights, build fp16 B-fragment tables, sniff mask dtype.
// ============================================================
__global__ void fold_kernel(const float* __restrict__ Wpre,
                            const float* __restrict__ g0,  const float* __restrict__ b0,
                            const float* __restrict__ m0,  const float* __restrict__ v0,
                            const float* __restrict__ W1,
                            const float* __restrict__ g1,  const float* __restrict__ bb1,
                            const float* __restrict__ m1,  const float* __restrict__ v1,
                            const float* __restrict__ W2,
                            const float* __restrict__ g2,  const float* __restrict__ bb2,
                            const float* __restrict__ m2,  const float* __restrict__ v2,
                            const float* __restrict__ W3,
                            const float* __restrict__ W4,
                            const void*  __restrict__ mask)
{
    __shared__ float s0[H_], s1[H_], s2[H_];
    __shared__ unsigned red[3];
    const int tid = threadIdx.x;

    if (tid < 3) red[tid] = 0u;
    if (tid < H_) {
        float sc0 = g0[tid] * rsqrtf(v0[tid] + BN_EPS);
        float sc1 = g1[tid] * rsqrtf(v1[tid] + BN_EPS);
        float sc2 = g2[tid] * rsqrtf(v2[tid] + BN_EPS);
        s0[tid] = sc0; s1[tid] = sc1; s2[tid] = sc2;
        g_b0v[tid] = b0[tid]  - m0[tid] * sc0;
        g_b1v[tid] = bb1[tid] - m1[tid] * sc1;
        g_b2v[tid] = bb2[tid] - m2[tid] * sc2;
    }
    __syncthreads();

    // fp16 B-frag (m16n8k16): reg r holds half2 {W[k0][h], W[k0+1][h]},
    // k0 = kt*16 + (lane&3)*2 + r*8, h = n-tile*8 + (lane>>2)

    // Wpre (single k-step, C=9 zero-padded to 16)
    for (int i = tid; i < 512; i += blockDim.x) {
        int r = i & 1, lane = (i >> 1) & 31, t = (i >> 6) & 3, w = (i >> 8) & 1;
        int k0 = (lane & 3) * 2 + r * 8;
        int h  = w * 32 + t * 8 + (lane >> 2);
        float va = (k0     < C_) ? Wpre[k0 * H_ + h]       * s0[h] : 0.0f;
        float vb = (k0 + 1 < C_) ? Wpre[(k0 + 1) * H_ + h] * s0[h] : 0.0f;
        g_W0h[i] = packh2(va, vb);
    }

    // W1 (both halves), W2, W3: [64][64] fp16 frags (4 k-steps of 16)
    for (int i = tid; i < 2048; i += blockDim.x) {
        int r = i & 1, lane = (i >> 1) & 31, t = (i >> 6) & 3, kt = (i >> 8) & 3, w = (i >> 10) & 1;
        int k0 = kt * 16 + (lane & 3) * 2 + r * 8;
        int h  = w * 32 + t * 8 + (lane >> 2);
        g_W1h[i]  = packh2(W1[k0 * H_ + h] * s1[h],        W1[(k0 + 1) * H_ + h] * s1[h]);
        g_W1hh[i] = packh2(W1[(H_ + k0) * H_ + h] * s1[h], W1[(H_ + k0 + 1) * H_ + h] * s1[h]);
        g_W2h[i]  = packh2(W2[k0 * H_ + h] * s2[h],        W2[(k0 + 1) * H_ + h] * s2[h]);
        g_W3h[i]  = packh2(W3[k0 * H_ + h],                W3[(k0 + 1) * H_ + h]);
    }

    // W4 [64][128]: 4 k-steps x 16 n-tiles (fp16)
    for (int i = tid; i < 4096; i += blockDim.x) {
        int r = i & 1, lane = (i >> 1) & 31, tt = (i >> 6) & 15, kt = (i >> 10) & 3;
        int k0 = kt * 16 + (lane & 3) * 2 + r * 8;
        int o  = tt * 8 + (lane >> 2);
        g_W4h[i] = packh2(W4[k0 * OUT_ + o], W4[(k0 + 1) * OUT_ + o]);
    }

    // Parallel mask dtype sniff (first 1024 bytes).
    {
        const unsigned char* mb = (const unsigned char*)mask;
        unsigned mx = 0, off = 0, al = 0;
        for (int i = tid * 4; i < tid * 4 + 4; i++) {
            unsigned v = mb[i];
            mx |= v;
            if ((i & 3) != 0) off |= v; else al |= v;
        }
        atomicOr(&red[0], mx);
        atomicOr(&red[1], off);
        atomicOr(&red[2], al);
        __syncthreads();
        if (tid == 0)
            g_mask4 = (red[0] > 1u) || (red[1] == 0u && red[2] != 0u);
    }
}

// ============================================================
// Fused encoder: 4 polylines per CTA, 256 threads (8 warps), all-fp16 mma.
// X0 lives in sA, X1 in sB (double-buffered: no in-place store hazard).
// The input tile sP overlays the head of sB (dead by the time X1 is written).
// A-fragments loaded via ldmatrix.x4.
// ============================================================
__global__ __launch_bounds__(256, 4) void pnet_kernel(
    const float* __restrict__ poly,   // [NPOLY, N, C]
    const void*  __restrict__ mask,   // [NPOLY, N]
    const float* __restrict__ b3,     // [H]
    const float* __restrict__ b4,     // [OUT]
    float*       __restrict__ out,    // [NPOLY, OUT]
    int npoly)
{
    __shared__ __align__(16) uint32_t sA[4 * N_ * SAWH];  // X0 half2 per poly
    __shared__ __align__(16) uint32_t sB[4 * N_ * SAWH];  // input (phase0/1) then X1
    __shared__ float    sM[4 * N_];
    __shared__ uint32_t sPool1h[4 * SVH];                  // pooled1 as half2 rows
    __shared__ float    sT[4 * SVW];
    __shared__ uint32_t sPool3h[4 * SVH];                  // pooled3 as half2 rows
    __shared__ uint32_t sH4h[4 * SVH];                     // relu(W3 out) as half2 rows
    __shared__ __align__(16) float sOut[4 * 132];
    __shared__ int      sValid[4];

    const int tid  = threadIdx.x;
    const int lane = tid & 31;
    const int wid  = tid >> 5;
    const int p    = wid >> 1;      // poly slot
    const int w    = wid & 1;       // N-half / h-half
    const int pid  = blockIdx.x * 4 + p;
    const int r0   = lane >> 2;
    const int c0   = lane & 3;
    const bool vp  = pid < npoly;
    const __half2 hz = __float2half2_rn(0.0f);

    uint32_t* const sAp = sA + p * (N_ * SAWH);
    uint32_t* const sBp = sB + p * (N_ * SAWH);
    uint32_t* const sPp = sB + p * (N_ * SPWH);   // input tile overlays sB head

    // ldmatrix per-lane addresses
    const int rowA  = lane & 15;          // row within 16-row block
    const int khalf = lane >> 4;          // 0: k 0..7, 1: k 8..15 (words +4)
    const uint32_t sAbase = (uint32_t)__cvta_generic_to_shared(sAp)
                          + (rowA * SAWH + khalf * 4) * 4;
    const uint32_t sBbase = (uint32_t)__cvta_generic_to_shared(sBp)
                          + (rowA * SAWH + khalf * 4) * 4;
    const uint32_t sPbase = (uint32_t)__cvta_generic_to_shared(sPp)
                          + (rowA * SPWH + khalf * 4) * 4;

    // ---------------- phase 0: load points (fp16, zero-padded k) + mask ----------------
    {
        const float* pp = poly + (size_t)pid * (N_ * C_);
        __half* sPh = (__half*)sPp;
        int q = w * 32 + lane;
        for (int i = q; i < N_ * 16; i += 64) {
            int n = i >> 4, c = i & 15;
            float v = (vp && c < C_) ? pp[n * C_ + c] : 0.0f;
            sPh[n * (2 * SPWH) + c] = __float2half_rn(v);
        }
        if (q < N_) {
            bool valid = false;
            if (vp) {
                size_t idx = (size_t)pid * N_ + q;
                valid = g_mask4 ? (((const unsigned*)mask)[idx] != 0u)
                                : (((const unsigned char*)mask)[idx] != 0u);
            }
            sM[p * N_ + q] = valid ? 1.0f : 0.0f;
            if (q == 0) sValid[p] = 0;
        }
    }
    BARP(1 + p);
    {
        int q = w * 32 + lane;
        if (q < N_ && sM[p * N_ + q] != 0.0f) sValid[p] = 1;  // benign: all store 1
    }

    float acc[2][4][4];

    // ---------------- stage 1: X0 = relu(P @ Wpre' + b0') * mask (1 k-step) ----------------
    {
        #pragma unroll
        for (int t = 0; t < 4; t++) {
            int hc = w * 32 + t * 8 + c0 * 2;
            float v0 = g_b0v[hc], v1 = g_b0v[hc + 1];
            #pragma unroll
            for (int m = 0; m < 2; m++) {
                acc[m][t][0] = v0; acc[m][t][1] = v1;
                acc[m][t][2] = v0; acc[m][t][3] = v1;
            }
        }
        uint32_t a[2][4];
        #pragma unroll
        for (int m = 0; m < 2; m++)
            ldsm4(a[m][0], a[m][1], a[m][2], a[m][3], sPbase + m * (16 * SPWH * 4));
        const uint32_t* Wf = g_W0h + w * 256;
        #pragma unroll
        for (int t = 0; t < 4; t++) {
            uint2 b = *(const uint2*)(Wf + (t * 32 + lane) * 2);
            #pragma unroll
            for (int m = 0; m < 2; m++)
                mma_f16(acc[m][t][0], acc[m][t][1], acc[m][t][2], acc[m][t][3],
                        a[m][0], a[m][1], a[m][2], a[m][3], b.x, b.y);
        }
        // epilogue: relu*mask + store X0 + pool, all in half2
        uint32_t pm[4] = {0, 0, 0, 0};
        #pragma unroll
        for (int m = 0; m < 2; m++) {
            __half2 mk0 = __float2half2_rn(sM[p * N_ + m * 16 + r0]);
            __half2 mk1 = __float2half2_rn(sM[p * N_ + m * 16 + r0 + 8]);
            #pragma unroll
            for (int t = 0; t < 4; t++) {
                int wc = w * 16 + t * 4 + c0;
                int nb = (m * 16 + r0) * SAWH;
                __half2 a01 = __hmul2(__hmax2(__floats2half2_rn(acc[m][t][0], acc[m][t][1]), hz), mk0);
                __half2 a23 = __hmul2(__hmax2(__floats2half2_rn(acc[m][t][2], acc[m][t][3]), hz), mk1);
                sAp[nb + wc]            = h2bits(a01);
                sAp[nb + 8 * SAWH + wc] = h2bits(a23);
                pm[t] = h2bits(__hmax2(bits2h(pm[t]), __hmax2(a01, a23)));
            }
        }
        #pragma unroll
        for (int s = 4; s < 32; s <<= 1) {
            #pragma unroll
            for (int t = 0; t < 4; t++)
                pm[t] = h2bits(__hmax2(bits2h(pm[t]),
                                       bits2h(__shfl_xor_sync(0xFFFFFFFFu, pm[t], s))));
        }
        if (r0 == 0) {
            #pragma unroll
            for (int t = 0; t < 4; t++)
                sPool1h[p * SVH + w * 16 + t * 4 + c0] = pm[t];
        }
    }
    __syncthreads();

    // ---------------- sT = b1' + pooled1 @ W1_hi  (fp16, M=4, all 8 warps) ----------------
    {
        const int tw = wid >> 2, tt4 = wid & 3;
        const int hc = wid * 8 + c0 * 2;
        float d0 = g_b1v[hc], d1 = g_b1v[hc + 1], d2 = 0.0f, d3 = 0.0f;
        #pragma unroll
        for (int kt = 0; kt < 4; kt++) {
            uint32_t a0 = 0, a2 = 0;
            if (r0 < 4) {
                a0 = sPool1h[r0 * SVH + kt * 8 + c0];
                a2 = sPool1h[r0 * SVH + kt * 8 + 4 + c0];
            }
            uint2 b = *(const uint2*)(g_W1hh + (((tw * 4 + kt) * 4 + tt4) * 32 + lane) * 2);
            mma_f16(d0, d1, d2, d3, a0, 0u, a2, 0u, b.x, b.y);
        }
        if (r0 < 4) {
            sT[r0 * SVW + hc]     = d0;
            sT[r0 * SVW + hc + 1] = d1;
        }
    }
    __syncthreads();   // sT visible; also: all sP reads done -> sB reusable for X1

    // ---------------- stage 2: X1 = relu(X0 @ W1_lo + t) * mask  (X1 -> sB) ----------------
    {
        #pragma unroll
        for (int t = 0; t < 4; t++) {
            int hc = w * 32 + t * 8 + c0 * 2;
            float v0 = sT[p * SVW + hc], v1 = sT[p * SVW + hc + 1];
            #pragma unroll
            for (int m = 0; m < 2; m++) {
                acc[m][t][0] = v0; acc[m][t][1] = v1;
                acc[m][t][2] = v0; acc[m][t][3] = v1;
            }
        }
        const uint32_t* Wf = g_W1h + w * 1024;
        #pragma unroll
        for (int kt = 0; kt < 4; kt++) {
            uint32_t a[2][4];
            #pragma unroll
            for (int m = 0; m < 2; m++)
                ldsm4(a[m][0], a[m][1], a[m][2], a[m][3],
                      sAbase + m * (16 * SAWH * 4) + kt * 32);
            #pragma unroll
            for (int t = 0; t < 4; t++) {
                uint2 b = *(const uint2*)(Wf + ((kt * 4 + t) * 32 + lane) * 2);
                #pragma unroll
                for (int m = 0; m < 2; m++)
                    mma_f16(acc[m][t][0], acc[m][t][1], acc[m][t][2], acc[m][t][3],
                            a[m][0], a[m][1], a[m][2], a[m][3], b.x, b.y);
            }
        }
        // epilogue straight to sB — no hazard with X0 (different buffer)
        #pragma unroll
        for (int m = 0; m < 2; m++) {
            __half2 mk0 = __float2half2_rn(sM[p * N_ + m * 16 + r0]);
            __half2 mk1 = __float2half2_rn(sM[p * N_ + m * 16 + r0 + 8]);
            #pragma unroll
            for (int t = 0; t < 4; t++) {
                int wc = w * 16 + t * 4 + c0;
                int nb = (m * 16 + r0) * SAWH;
                sBp[nb + wc]            = h2bits(__hmul2(__hmax2(
                    __floats2half2_rn(acc[m][t][0], acc[m][t][1]), hz), mk0));
                sBp[nb + 8 * SAWH + wc] = h2bits(__hmul2(__hmax2(
                    __floats2half2_rn(acc[m][t][2], acc[m][t][3]), hz), mk1));
            }
        }
    }
    BARP(1 + p);   // pair's X1 half visible before stage 3

    // ---------------- stage 3: relu(X1 @ W2 + b2') * mask -> pool (regs only) ----------------
    {
        #pragma unroll
        for (int t = 0; t < 4; t++) {
            int hc = w * 32 + t * 8 + c0 * 2;
            float v0 = g_b2v[hc], v1 = g_b2v[hc + 1];
            #pragma unroll
            for (int m = 0; m < 2; m++) {
                acc[m][t][0] = v0; acc[m][t][1] = v1;
                acc[m][t][2] = v0; acc[m][t][3] = v1;
            }
        }
        const uint32_t* Wf = g_W2h + w * 1024;
        #pragma unroll
        for (int kt = 0; kt < 4; kt++) {
            uint32_t a[2][4];
            #pragma unroll
            for (int m = 0; m < 2; m++)
                ldsm4(a[m][0], a[m][1], a[m][2], a[m][3],
                      sBbase + m * (16 * SAWH * 4) + kt * 32);
            #pragma unroll
            for (int t = 0; t < 4; t++) {
                uint2 b = *(const uint2*)(Wf + ((kt * 4 + t) * 32 + lane) * 2);
                #pragma unroll
                for (int m = 0; m < 2; m++)
                    mma_f16(acc[m][t][0], acc[m][t][1], acc[m][t][2], acc[m][t][3],
                            a[m][0], a[m][1], a[m][2], a[m][3], b.x, b.y);
            }
        }
        // epilogue: relu*mask -> pool via half2 + shfl (no X2 store)
        uint32_t pm[4] = {0, 0, 0, 0};
        #pragma unroll
        for (int m = 0; m < 2; m++) {
            __half2 mk0 = __float2half2_rn(sM[p * N_ + m * 16 + r0]);
            __half2 mk1 = __float2half2_rn(sM[p * N_ + m * 16 + r0 + 8]);
            #pragma unroll
            for (int t = 0; t < 4; t++) {
                __half2 a01 = __hmul2(__hmax2(__floats2half2_rn(acc[m][t][0], acc[m][t][1]), hz), mk0);
                __half2 a23 = __hmul2(__hmax2(__floats2half2_rn(acc[m][t][2], acc[m][t][3]), hz), mk1);
                pm[t] = h2bits(__hmax2(bits2h(pm[t]), __hmax2(a01, a23)));
            }
        }
        #pragma unroll
        for (int s = 4; s < 32; s <<= 1) {
            #pragma unroll
            for (int t = 0; t < 4; t++)
                pm[t] = h2bits(__hmax2(bits2h(pm[t]),
                                       bits2h(__shfl_xor_sync(0xFFFFFFFFu, pm[t], s))));
        }
        if (r0 == 0) {
            #pragma unroll
            for (int t = 0; t < 4; t++)
                sPool3h[p * SVH + w * 16 + t * 4 + c0] = pm[t];
        }
    }
    __syncthreads();

    // ---------------- head part 1: H4 = relu(pooled3 @ W3 + b3)  (fp16, M=4) ----------------
    {
        const int tw = wid >> 2, tt4 = wid & 3;
        const int hc = wid * 8 + c0 * 2;
        float d0 = b3[hc], d1 = b3[hc + 1], d2 = 0.0f, d3 = 0.0f;
        #pragma unroll
        for (int kt = 0; kt < 4; kt++) {
            uint32_t a0 = 0, a2 = 0;
            if (r0 < 4) {
                a0 = sPool3h[r0 * SVH + kt * 8 + c0];
                a2 = sPool3h[r0 * SVH + kt * 8 + 4 + c0];
            }
            uint2 b = *(const uint2*)(g_W3h + (((tw * 4 + kt) * 4 + tt4) * 32 + lane) * 2);
            mma_f16(d0, d1, d2, d3, a0, 0u, a2, 0u, b.x, b.y);
        }
        if (r0 < 4)
            sH4h[r0 * SVH + wid * 4 + c0] = packh2(fmaxf(d0, 0.0f), fmaxf(d1, 0.0f));
    }
    __syncthreads();

    // ---------------- head part 2: out = (H4 @ W4 + b4) * anyvalid  (fp16, M=4, N=128) ----------------
    {
        const int tt0 = wid * 2;
        float e0[2], e1[2], e2[2], e3[2];
        #pragma unroll
        for (int j = 0; j < 2; j++) {
            int o = (tt0 + j) * 8 + c0 * 2;
            e0[j] = b4[o]; e1[j] = b4[o + 1]; e2[j] = 0.0f; e3[j] = 0.0f;
        }
        #pragma unroll
        for (int kt = 0; kt < 4; kt++) {
            uint32_t a0 = 0, a2 = 0;
            if (r0 < 4) {
                a0 = sH4h[r0 * SVH + kt * 8 + c0];
                a2 = sH4h[r0 * SVH + kt * 8 + 4 + c0];
            }
            #pragma unroll
            for (int j = 0; j < 2; j++) {
                uint2 b = *(const uint2*)(g_W4h + ((kt * 16 + tt0 + j) * 32 + lane) * 2);
                mma_f16(e0[j], e1[j], e2[j], e3[j], a0, 0u, a2, 0u, b.x, b.y);
            }
        }
        if (r0 < 4) {
            float vf = sValid[r0] ? 1.0f : 0.0f;
            #pragma unroll
            for (int j = 0; j < 2; j++) {
                int o = (tt0 + j) * 8 + c0 * 2;
                sOut[r0 * 132 + o]     = e0[j] * vf;
                sOut[r0 * 132 + o + 1] = e1[j] * vf;
            }
        }
    }
    __syncthreads();

    // ---------------- coalesced store ----------------
    if (tid < 128) {
        int pp = tid >> 5, j = tid & 31;
        int opid = blockIdx.x * 4 + pp;
        if (opid < npoly) {
            float4 v = *(const float4*)(sOut + pp * 132 + j * 4);
            *(float4*)(out + (size_t)opid * OUT_ + j * 4) = v;
        }
    }
}

// ============================================================
// Launch
// ============================================================
extern "C" void kernel_launch(void* const* d_in, const int* in_sizes, int n_in,
                              void* d_out, int out_size)
{
    const float* poly = (const float*)d_in[0];
    const float* Wpre = (const float*)d_in[1];
    const float* g0   = (const float*)d_in[2];
    const float* b0   = (const float*)d_in[3];
    const float* m0   = (const float*)d_in[4];
    const float* v0   = (const float*)d_in[5];
    const float* W1   = (const float*)d_in[6];
    const float* g1   = (const float*)d_in[7];
    const float* bb1  = (const float*)d_in[8];
    const float* m1   = (const float*)d_in[9];
    const float* v1   = (const float*)d_in[10];
    const float* W2   = (const float*)d_in[11];
    const float* g2   = (const float*)d_in[12];
    const float* bb2  = (const float*)d_in[13];
    const float* m2   = (const float*)d_in[14];
    const float* v2   = (const float*)d_in[15];
    const float* W3   = (const float*)d_in[16];
    const float* b3   = (const float*)d_in[17];
    const float* W4   = (const float*)d_in[18];
    const float* b4   = (const float*)d_in[19];
    const void*  mask = d_in[20];

    const int npoly = in_sizes[0] / (N_ * C_);

    fold_kernel<<<1, 256>>>(Wpre, g0, b0, m0, v0,
                            W1, g1, bb1, m1, v1,
                            W2, g2, bb2, m2, v2, W3, W4, mask);
    pnet_kernel<<<(npoly + 3) / 4, 256>>>(poly, mask, b3, b4, (float*)d_out, npoly);
}

// round 9
// speedup vs baseline: 1.0008x; 1.0008x over previous
#include <cuda_runtime.h>
#include <cuda_fp16.h>
#include <cstdint>

#define BN_EPS 1e-5f

constexpr int N_    = 32;   // points per polyline
constexpr int C_    = 9;    // input channels
constexpr int H_    = 64;   // hidden
constexpr int OUT_  = 128;
constexpr int SAWH  = 36;   // X tile row stride in half2-words -> conflict-free frags
constexpr int SPWH  = 12;   // P tile row stride in half2-words -> conflict-free
constexpr int SVH   = 36;   // row stride (half2 words) for [4][32] pooled / H4 mats
constexpr int SVW   = 68;   // row stride (f32) for sT

// -------- device scratch (no allocations allowed) --------
__device__ float    g_b0v[H_], g_b1v[H_], g_b2v[H_];
__device__ uint32_t g_W0h[512];         // folded Wpre (k padded to 16), fp16 B-frag
__device__ uint32_t g_W1h[2048];        // folded W1 low half  (k 0..63), fp16 B-frag
__device__ uint32_t g_W1hh[2048];       // folded W1 high half (k 64..127), fp16 B-frag
__device__ uint32_t g_W2h[2048];        // folded W2, fp16 B-frag
__device__ uint32_t g_W3h[2048];        // raw W3, fp16 B-frag
__device__ uint32_t g_W4h[4096];        // raw W4 [64][128], fp16 B-frag
__device__ int      g_mask4;            // 1 if mask elements are 4 bytes wide

__device__ __forceinline__ uint32_t packh2(float a, float b) {
    __half2 h = __floats2half2_rn(a, b);
    return *(uint32_t*)&h;
}
__device__ __forceinline__ uint32_t h2bits(__half2 v) { return *(uint32_t*)&v; }
__device__ __forceinline__ __half2  bits2h(uint32_t u) { return *(__half2*)&u; }

__device__ __forceinline__ void mma_f16(float& c0, float& c1, float& c2, float& c3,
                                        uint32_t a0, uint32_t a1, uint32_t a2, uint32_t a3,
                                        uint32_t b0, uint32_t b1) {
    asm volatile(
        "mma.sync.aligned.m16n8k16.row.col.f32.f16.f16.f32 "
        "{%0,%1,%2,%3},{%4,%5,%6,%7},{%8,%9},{%0,%1,%2,%3};\n"
        : "+f"(c0), "+f"(c1), "+f"(c2), "+f"(c3)
        : "r"(a0), "r"(a1), "r"(a2), "r"(a3), "r"(b0), "r"(b1));
}

#define BARP(id) asm volatile("bar.sync %0, %1;" :: "r"(id), "r"(64) : "memory")

// ============================================================
// Fold BN into weights, build fp16 B-fragment tables, sniff mask dtype.
// ============================================================
__global__ void fold_kernel(const float* __restrict__ Wpre,
                            const float* __restrict__ g0,  const float* __restrict__ b0,
                            const float* __restrict__ m0,  const float* __restrict__ v0,
                            const float* __restrict__ W1,
                            const float* __restrict__ g1,  const float* __restrict__ bb1,
                            const float* __restrict__ m1,  const float* __restrict__ v1,
                            const float* __restrict__ W2,
                            const float* __restrict__ g2,  const float* __restrict__ bb2,
                            const float* __restrict__ m2,  const float* __restrict__ v2,
                            const float* __restrict__ W3,
                            const float* __restrict__ W4,
                            const void*  __restrict__ mask)
{
    __shared__ float s0[H_], s1[H_], s2[H_];
    __shared__ unsigned red[3];
    const int tid = threadIdx.x;

    if (tid < 3) red[tid] = 0u;
    if (tid < H_) {
        float sc0 = g0[tid] * rsqrtf(v0[tid] + BN_EPS);
        float sc1 = g1[tid] * rsqrtf(v1[tid] + BN_EPS);
        float sc2 = g2[tid] * rsqrtf(v2[tid] + BN_EPS);
        s0[tid] = sc0; s1[tid] = sc1; s2[tid] = sc2;
        g_b0v[tid] = b0[tid]  - m0[tid] * sc0;
        g_b1v[tid] = bb1[tid] - m1[tid] * sc1;
        g_b2v[tid] = bb2[tid] - m2[tid] * sc2;
    }
    __syncthreads();

    // fp16 B-frag (m16n8k16): reg r holds half2 {W[k0][h], W[k0+1][h]},
    // k0 = kt*16 + (lane&3)*2 + r*8, h = n-tile*8 + (lane>>2)

    // Wpre (single k-step, C=9 zero-padded to 16)
    for (int i = tid; i < 512; i += blockDim.x) {
        int r = i & 1, lane = (i >> 1) & 31, t = (i >> 6) & 3, w = (i >> 8) & 1;
        int k0 = (lane & 3) * 2 + r * 8;
        int h  = w * 32 + t * 8 + (lane >> 2);
        float va = (k0     < C_) ? Wpre[k0 * H_ + h]       * s0[h] : 0.0f;
        float vb = (k0 + 1 < C_) ? Wpre[(k0 + 1) * H_ + h] * s0[h] : 0.0f;
        g_W0h[i] = packh2(va, vb);
    }

    // W1 (both halves), W2, W3: [64][64] fp16 frags (4 k-steps of 16)
    for (int i = tid; i < 2048; i += blockDim.x) {
        int r = i & 1, lane = (i >> 1) & 31, t = (i >> 6) & 3, kt = (i >> 8) & 3, w = (i >> 10) & 1;
        int k0 = kt * 16 + (lane & 3) * 2 + r * 8;
        int h  = w * 32 + t * 8 + (lane >> 2);
        g_W1h[i]  = packh2(W1[k0 * H_ + h] * s1[h],        W1[(k0 + 1) * H_ + h] * s1[h]);
        g_W1hh[i] = packh2(W1[(H_ + k0) * H_ + h] * s1[h], W1[(H_ + k0 + 1) * H_ + h] * s1[h]);
        g_W2h[i]  = packh2(W2[k0 * H_ + h] * s2[h],        W2[(k0 + 1) * H_ + h] * s2[h]);
        g_W3h[i]  = packh2(W3[k0 * H_ + h],                W3[(k0 + 1) * H_ + h]);
    }

    // W4 [64][128]: 4 k-steps x 16 n-tiles (fp16)
    for (int i = tid; i < 4096; i += blockDim.x) {
        int r = i & 1, lane = (i >> 1) & 31, tt = (i >> 6) & 15, kt = (i >> 10) & 3;
        int k0 = kt * 16 + (lane & 3) * 2 + r * 8;
        int o  = tt * 8 + (lane >> 2);
        g_W4h[i] = packh2(W4[k0 * OUT_ + o], W4[(k0 + 1) * OUT_ + o]);
    }

    // Parallel mask dtype sniff (first 1024 bytes).
    {
        const unsigned char* mb = (const unsigned char*)mask;
        unsigned mx = 0, off = 0, al = 0;
        for (int i = tid * 4; i < tid * 4 + 4; i++) {
            unsigned v = mb[i];
            mx |= v;
            if ((i & 3) != 0) off |= v; else al |= v;
        }
        atomicOr(&red[0], mx);
        atomicOr(&red[1], off);
        atomicOr(&red[2], al);
        __syncthreads();
        if (tid == 0)
            g_mask4 = (red[0] > 1u) || (red[1] == 0u && red[2] != 0u);
    }
}

// ============================================================
// Fused encoder: 4 polylines per CTA, 256 threads (8 warps), all-fp16 mma.
// Round-7 structure (scalar LDS A-frag loads) + X0/X1 double buffer:
// X0 in sA, X1 in sB (input tile overlays sB head, dead after stage 1).
// ============================================================
__global__ __launch_bounds__(256, 4) void pnet_kernel(
    const float* __restrict__ poly,   // [NPOLY, N, C]
    const void*  __restrict__ mask,   // [NPOLY, N]
    const float* __restrict__ b3,     // [H]
    const float* __restrict__ b4,     // [OUT]
    float*       __restrict__ out,    // [NPOLY, OUT]
    int npoly)
{
    __shared__ __align__(16) uint32_t sA[4 * N_ * SAWH];  // X0 half2 per poly
    __shared__ __align__(16) uint32_t sB[4 * N_ * SAWH];  // input (phase0/1) then X1
    __shared__ float    sM[4 * N_];
    __shared__ uint32_t sPool1h[4 * SVH];                  // pooled1 as half2 rows
    __shared__ float    sT[4 * SVW];
    __shared__ uint32_t sPool3h[4 * SVH];                  // pooled3 as half2 rows
    __shared__ uint32_t sH4h[4 * SVH];                     // relu(W3 out) as half2 rows
    __shared__ __align__(16) float sOut[4 * 132];
    __shared__ int      sValid[4];

    const int tid  = threadIdx.x;
    const int lane = tid & 31;
    const int wid  = tid >> 5;
    const int p    = wid >> 1;      // poly slot
    const int w    = wid & 1;       // N-half / h-half
    const int pid  = blockIdx.x * 4 + p;
    const int r0   = lane >> 2;
    const int c0   = lane & 3;
    const bool vp  = pid < npoly;
    const __half2 hz = __float2half2_rn(0.0f);

    uint32_t* const sAp = sA + p * (N_ * SAWH);
    uint32_t* const sBp = sB + p * (N_ * SAWH);
    uint32_t* const sPp = sB + p * (N_ * SPWH);   // input tile overlays sB head

    // ---------------- phase 0: load points (fp16, zero-padded k) + mask ----------------
    {
        const float* pp = poly + (size_t)pid * (N_ * C_);
        __half* sPh = (__half*)sPp;
        int q = w * 32 + lane;
        for (int i = q; i < N_ * 16; i += 64) {
            int n = i >> 4, c = i & 15;
            float v = (vp && c < C_) ? pp[n * C_ + c] : 0.0f;
            sPh[n * (2 * SPWH) + c] = __float2half_rn(v);
        }
        if (q < N_) {
            bool valid = false;
            if (vp) {
                size_t idx = (size_t)pid * N_ + q;
                valid = g_mask4 ? (((const unsigned*)mask)[idx] != 0u)
                                : (((const unsigned char*)mask)[idx] != 0u);
            }
            sM[p * N_ + q] = valid ? 1.0f : 0.0f;
            if (q == 0) sValid[p] = 0;
        }
    }
    BARP(1 + p);
    {
        int q = w * 32 + lane;
        if (q < N_ && sM[p * N_ + q] != 0.0f) sValid[p] = 1;  // benign: all store 1
    }

    float acc[2][4][4];

    // ---------------- stage 1: X0 = relu(P @ Wpre' + b0') * mask (1 k-step) ----------------
    {
        #pragma unroll
        for (int t = 0; t < 4; t++) {
            int hc = w * 32 + t * 8 + c0 * 2;
            float v0 = g_b0v[hc], v1 = g_b0v[hc + 1];
            #pragma unroll
            for (int m = 0; m < 2; m++) {
                acc[m][t][0] = v0; acc[m][t][1] = v1;
                acc[m][t][2] = v0; acc[m][t][3] = v1;
            }
        }
        uint32_t a[2][4];
        #pragma unroll
        for (int m = 0; m < 2; m++) {
            int base = (m * 16 + r0) * SPWH + c0;
            a[m][0] = sPp[base];
            a[m][1] = sPp[base + 8 * SPWH];
            a[m][2] = sPp[base + 4];
            a[m][3] = sPp[base + 8 * SPWH + 4];
        }
        const uint32_t* Wf = g_W0h + w * 256;
        #pragma unroll
        for (int t = 0; t < 4; t++) {
            uint2 b = *(const uint2*)(Wf + (t * 32 + lane) * 2);
            #pragma unroll
            for (int m = 0; m < 2; m++)
                mma_f16(acc[m][t][0], acc[m][t][1], acc[m][t][2], acc[m][t][3],
                        a[m][0], a[m][1], a[m][2], a[m][3], b.x, b.y);
        }
        // epilogue: relu*mask + store X0 + pool, all in half2
        uint32_t pm[4] = {0, 0, 0, 0};
        #pragma unroll
        for (int m = 0; m < 2; m++) {
            __half2 mk0 = __float2half2_rn(sM[p * N_ + m * 16 + r0]);
            __half2 mk1 = __float2half2_rn(sM[p * N_ + m * 16 + r0 + 8]);
            #pragma unroll
            for (int t = 0; t < 4; t++) {
                int wc = w * 16 + t * 4 + c0;
                int nb = (m * 16 + r0) * SAWH;
                __half2 a01 = __hmul2(__hmax2(__floats2half2_rn(acc[m][t][0], acc[m][t][1]), hz), mk0);
                __half2 a23 = __hmul2(__hmax2(__floats2half2_rn(acc[m][t][2], acc[m][t][3]), hz), mk1);
                sAp[nb + wc]            = h2bits(a01);
                sAp[nb + 8 * SAWH + wc] = h2bits(a23);
                pm[t] = h2bits(__hmax2(bits2h(pm[t]), __hmax2(a01, a23)));
            }
        }
        #pragma unroll
        for (int s = 4; s < 32; s <<= 1) {
            #pragma unroll
            for (int t = 0; t < 4; t++)
                pm[t] = h2bits(__hmax2(bits2h(pm[t]),
                                       bits2h(__shfl_xor_sync(0xFFFFFFFFu, pm[t], s))));
        }
        if (r0 == 0) {
            #pragma unroll
            for (int t = 0; t < 4; t++)
                sPool1h[p * SVH + w * 16 + t * 4 + c0] = pm[t];
        }
    }
    __syncthreads();

    // ---------------- sT = b1' + pooled1 @ W1_hi  (fp16, M=4, all 8 warps) ----------------
    {
        const int tw = wid >> 2, tt4 = wid & 3;
        const int hc = wid * 8 + c0 * 2;
        float d0 = g_b1v[hc], d1 = g_b1v[hc + 1], d2 = 0.0f, d3 = 0.0f;
        #pragma unroll
        for (int kt = 0; kt < 4; kt++) {
            uint32_t a0 = 0, a2 = 0;
            if (r0 < 4) {
                a0 = sPool1h[r0 * SVH + kt * 8 + c0];
                a2 = sPool1h[r0 * SVH + kt * 8 + 4 + c0];
            }
            uint2 b = *(const uint2*)(g_W1hh + (((tw * 4 + kt) * 4 + tt4) * 32 + lane) * 2);
            mma_f16(d0, d1, d2, d3, a0, 0u, a2, 0u, b.x, b.y);
        }
        if (r0 < 4) {
            sT[r0 * SVW + hc]     = d0;
            sT[r0 * SVW + hc + 1] = d1;
        }
    }
    __syncthreads();   // sT visible; also: all sP reads done -> sB reusable for X1

    // ---------------- stage 2: X1 = relu(X0 @ W1_lo + t) * mask  (X1 -> sB) ----------------
    {
        #pragma unroll
        for (int t = 0; t < 4; t++) {
            int hc = w * 32 + t * 8 + c0 * 2;
            float v0 = sT[p * SVW + hc], v1 = sT[p * SVW + hc + 1];
            #pragma unroll
            for (int m = 0; m < 2; m++) {
                acc[m][t][0] = v0; acc[m][t][1] = v1;
                acc[m][t][2] = v0; acc[m][t][3] = v1;
            }
        }
        const uint32_t* Wf = g_W1h + w * 1024;
        #pragma unroll
        for (int kt = 0; kt < 4; kt++) {
            uint32_t a[2][4];
            #pragma unroll
            for (int m = 0; m < 2; m++) {
                int base = (m * 16 + r0) * SAWH + kt * 8 + c0;
                a[m][0] = sAp[base];
                a[m][1] = sAp[base + 8 * SAWH];
                a[m][2] = sAp[base + 4];
                a[m][3] = sAp[base + 8 * SAWH + 4];
            }
            #pragma unroll
            for (int t = 0; t < 4; t++) {
                uint2 b = *(const uint2*)(Wf + ((kt * 4 + t) * 32 + lane) * 2);
                #pragma unroll
                for (int m = 0; m < 2; m++)
                    mma_f16(acc[m][t][0], acc[m][t][1], acc[m][t][2], acc[m][t][3],
                            a[m][0], a[m][1], a[m][2], a[m][3], b.x, b.y);
            }
        }
        // epilogue straight to sB — no hazard with X0 (different buffer), no barrier needed
        #pragma unroll
        for (int m = 0; m < 2; m++) {
            __half2 mk0 = __float2half2_rn(sM[p * N_ + m * 16 + r0]);
            __half2 mk1 = __float2half2_rn(sM[p * N_ + m * 16 + r0 + 8]);
            #pragma unroll
            for (int t = 0; t < 4; t++) {
                int wc = w * 16 + t * 4 + c0;
                int nb = (m * 16 + r0) * SAWH;
                sBp[nb + wc]            = h2bits(__hmul2(__hmax2(
                    __floats2half2_rn(acc[m][t][0], acc[m][t][1]), hz), mk0));
                sBp[nb + 8 * SAWH + wc] = h2bits(__hmul2(__hmax2(
                    __floats2half2_rn(acc[m][t][2], acc[m][t][3]), hz), mk1));
            }
        }
    }
    BARP(1 + p);   // pair's X1 half visible before stage 3

    // ---------------- stage 3: relu(X1 @ W2 + b2') * mask -> pool (regs only) ----------------
    {
        #pragma unroll
        for (int t = 0; t < 4; t++) {
            int hc = w * 32 + t * 8 + c0 * 2;
            float v0 = g_b2v[hc], v1 = g_b2v[hc + 1];
            #pragma unroll
            for (int m = 0; m < 2; m++) {
                acc[m][t][0] = v0; acc[m][t][1] = v1;
                acc[m][t][2] = v0; acc[m][t][3] = v1;
            }
        }
        const uint32_t* Wf = g_W2h + w * 1024;
        #pragma unroll
        for (int kt = 0; kt < 4; kt++) {
            uint32_t a[2][4];
            #pragma unroll
            for (int m = 0; m < 2; m++) {
                int base = (m * 16 + r0) * SAWH + kt * 8 + c0;
                a[m][0] = sBp[base];
                a[m][1] = sBp[base + 8 * SAWH];
                a[m][2] = sBp[base + 4];
                a[m][3] = sBp[base + 8 * SAWH + 4];
            }
            #pragma unroll
            for (int t = 0; t < 4; t++) {
                uint2 b = *(const uint2*)(Wf + ((kt * 4 + t) * 32 + lane) * 2);
                #pragma unroll
                for (int m = 0; m < 2; m++)
                    mma_f16(acc[m][t][0], acc[m][t][1], acc[m][t][2], acc[m][t][3],
                            a[m][0], a[m][1], a[m][2], a[m][3], b.x, b.y);
            }
        }
        // epilogue: relu*mask -> pool via half2 + shfl (no X2 store)
        uint32_t pm[4] = {0, 0, 0, 0};
        #pragma unroll
        for (int m = 0; m < 2; m++) {
            __half2 mk0 = __float2half2_rn(sM[p * N_ + m * 16 + r0]);
            __half2 mk1 = __float2half2_rn(sM[p * N_ + m * 16 + r0 + 8]);
            #pragma unroll
            for (int t = 0; t < 4; t++) {
                __half2 a01 = __hmul2(__hmax2(__floats2half2_rn(acc[m][t][0], acc[m][t][1]), hz), mk0);
                __half2 a23 = __hmul2(__hmax2(__floats2half2_rn(acc[m][t][2], acc[m][t][3]), hz), mk1);
                pm[t] = h2bits(__hmax2(bits2h(pm[t]), __hmax2(a01, a23)));
            }
        }
        #pragma unroll
        for (int s = 4; s < 32; s <<= 1) {
            #pragma unroll
            for (int t = 0; t < 4; t++)
                pm[t] = h2bits(__hmax2(bits2h(pm[t]),
                                       bits2h(__shfl_xor_sync(0xFFFFFFFFu, pm[t], s))));
        }
        if (r0 == 0) {
            #pragma unroll
            for (int t = 0; t < 4; t++)
                sPool3h[p * SVH + w * 16 + t * 4 + c0] = pm[t];
        }
    }
    __syncthreads();

    // ---------------- head part 1: H4 = relu(pooled3 @ W3 + b3)  (fp16, M=4) ----------------
    {
        const int tw = wid >> 2, tt4 = wid & 3;
        const int hc = wid * 8 + c0 * 2;
        float d0 = b3[hc], d1 = b3[hc + 1], d2 = 0.0f, d3 = 0.0f;
        #pragma unroll
        for (int kt = 0; kt < 4; kt++) {
            uint32_t a0 = 0, a2 = 0;
            if (r0 < 4) {
                a0 = sPool3h[r0 * SVH + kt * 8 + c0];
                a2 = sPool3h[r0 * SVH + kt * 8 + 4 + c0];
            }
            uint2 b = *(const uint2*)(g_W3h + (((tw * 4 + kt) * 4 + tt4) * 32 + lane) * 2);
            mma_f16(d0, d1, d2, d3, a0, 0u, a2, 0u, b.x, b.y);
        }
        if (r0 < 4)
            sH4h[r0 * SVH + wid * 4 + c0] = packh2(fmaxf(d0, 0.0f), fmaxf(d1, 0.0f));
    }
    __syncthreads();

    // ---------------- head part 2: out = (H4 @ W4 + b4) * anyvalid  (fp16, M=4, N=128) ----------------
    {
        const int tt0 = wid * 2;
        float e0[2], e1[2], e2[2], e3[2];
        #pragma unroll
        for (int j = 0; j < 2; j++) {
            int o = (tt0 + j) * 8 + c0 * 2;
            e0[j] = b4[o]; e1[j] = b4[o + 1]; e2[j] = 0.0f; e3[j] = 0.0f;
        }
        #pragma unroll
        for (int kt = 0; kt < 4; kt++) {
            uint32_t a0 = 0, a2 = 0;
            if (r0 < 4) {
                a0 = sH4h[r0 * SVH + kt * 8 + c0];
                a2 = sH4h[r0 * SVH + kt * 8 + 4 + c0];
            }
            #pragma unroll
            for (int j = 0; j < 2; j++) {
                uint2 b = *(const uint2*)(g_W4h + ((kt * 16 + tt0 + j) * 32 + lane) * 2);
                mma_f16(e0[j], e1[j], e2[j], e3[j], a0, 0u, a2, 0u, b.x, b.y);
            }
        }
        if (r0 < 4) {
            float vf = sValid[r0] ? 1.0f : 0.0f;
            #pragma unroll
            for (int j = 0; j < 2; j++) {
                int o = (tt0 + j) * 8 + c0 * 2;
                sOut[r0 * 132 + o]     = e0[j] * vf;
                sOut[r0 * 132 + o + 1] = e1[j] * vf;
            }
        }
    }
    __syncthreads();

    // ---------------- coalesced store ----------------
    if (tid < 128) {
        int pp = tid >> 5, j = tid & 31;
        int opid = blockIdx.x * 4 + pp;
        if (opid < npoly) {
            float4 v = *(const float4*)(sOut + pp * 132 + j * 4);
            *(float4*)(out + (size_t)opid * OUT_ + j * 4) = v;
        }
    }
}

// ============================================================
// Launch
// ============================================================
extern "C" void kernel_launch(void* const* d_in, const int* in_sizes, int n_in,
                              void* d_out, int out_size)
{
    const float* poly = (const float*)d_in[0];
    const float* Wpre = (const float*)d_in[1];
    const float* g0   = (const float*)d_in[2];
    const float* b0   = (const float*)d_in[3];
    const float* m0   = (const float*)d_in[4];
    const float* v0   = (const float*)d_in[5];
    const float* W1   = (const float*)d_in[6];
    const float* g1   = (const float*)d_in[7];
    const float* bb1  = (const float*)d_in[8];
    const float* m1   = (const float*)d_in[9];
    const float* v1   = (const float*)d_in[10];
    const float* W2   = (const float*)d_in[11];
    const float* g2   = (const float*)d_in[12];
    const float* bb2  = (const float*)d_in[13];
    const float* m2   = (const float*)d_in[14];
    const float* v2   = (const float*)d_in[15];
    const float* W3   = (const float*)d_in[16];
    const float* b3   = (const float*)d_in[17];
    const float* W4   = (const float*)d_in[18];
    const float* b4   = (const float*)d_in[19];
    const void*  mask = d_in[20];

    const int npoly = in_sizes[0] / (N_ * C_);

    fold_kernel<<<1, 256>>>(Wpre, g0, b0, m0, v0,
                            W1, g1, bb1, m1, v1,
                            W2, g2, bb2, m2, v2, W3, W4, mask);
    pnet_kernel<<<(npoly + 3) / 4, 256>>>(poly, mask, b3, b4, (float*)d_out, npoly);
}